// round 4
// baseline (speedup 1.0000x reference)
#include <cuda_runtime.h>
#include <cstdint>

// Problem constants
#define BB 2
#define DD 512
#define CC 512
#define TT 32
#define TDIM 1024
#define HH 8
#define FF 64
#define GR 32          // groups
#define CPG 16         // channels per group
#define SCALE 0.125f   // F^-0.5

#define M_QKV (BB*DD*TT)       // 32768
#define N_QKV (3*CC)           // 1536

// ---------------- scratch ----------------
__device__ float g_xt  [BB*DD*TT*CC];        // normalized, transposed x  [B,D,T,C]
__device__ float g_qkv [BB*DD*TT*3*CC];      // [B,D,T,3C]
__device__ float g_tprj[3*BB*TT*CC];         // [p,B,T,C]
__device__ float g_h   [3*BB*TT*TT*CC];      // silu(emb) [p,B,T,S,C]
__device__ float g_R   [3*BB*TT*TT*CC];      // rpe bias  [p,B,T,S,C]
__device__ float g_ao  [BB*DD*TT*CC];        // attention output pre-proj [B,D,T,C]

// ---------------- GroupNorm + transpose ----------------
// block per (b*D+d), 512 threads = 1 channel each; group stats over 16 ch x 32 t
__global__ __launch_bounds__(512) void groupnorm_kernel(
    const float* __restrict__ x, const float* __restrict__ w,
    const float* __restrict__ bv, float* __restrict__ xt)
{
    int bd = blockIdx.x;
    int c  = threadIdx.x;
    const float* xr = x + (size_t)bd * CC * TT + (size_t)c * TT;
    float v[TT];
    float s = 0.f, ss = 0.f;
#pragma unroll
    for (int i = 0; i < TT/4; i++) {
        float4 t4 = *(const float4*)(xr + i*4);
        v[i*4+0]=t4.x; v[i*4+1]=t4.y; v[i*4+2]=t4.z; v[i*4+3]=t4.w;
        s += t4.x+t4.y+t4.z+t4.w;
        ss += t4.x*t4.x + t4.y*t4.y + t4.z*t4.z + t4.w*t4.w;
    }
    // reduce over the 16 threads of this group (aligned 16-lane subgroups)
#pragma unroll
    for (int off = 8; off >= 1; off >>= 1) {
        s  += __shfl_xor_sync(0xffffffffu, s,  off);
        ss += __shfl_xor_sync(0xffffffffu, ss, off);
    }
    float mean = s * (1.f/512.f);
    float var  = ss * (1.f/512.f) - mean*mean;
    float rstd = rsqrtf(var + 1e-5f);
    float gw = w[c] * rstd;
    float gb = bv[c] - mean * gw;
    float* dst = xt + (size_t)bd * TT * CC + c;
#pragma unroll
    for (int t = 0; t < TT; t++) dst[(size_t)t*CC] = fmaf(v[t], gw, gb);
}

// ---------------- generic NT GEMM: out[m,n] = sum_k A[m,k]*W[n,k] + bias[n] ----------------
// BM=BN=64, BK=16, 256 threads, 4x4 per thread. M%64==0, N%64==0, K%16==0 required.
// MODE 0: plain row-major store. MODE 1: += resid[m*N+n], store transposed (N=512,T=32).
template<int MODE>
__global__ __launch_bounds__(256) void gemm_nt(
    const float* __restrict__ A, const float* __restrict__ W,
    const float* __restrict__ bias, float* __restrict__ out,
    const float* __restrict__ resid, int M, int N, int K)
{
    __shared__ float As[16][64];
    __shared__ float Ws[16][64];
    int bm = blockIdx.y * 64, bn = blockIdx.x * 64;
    int tid = threadIdx.x;
    int tx = tid & 15, ty = tid >> 4;
    int lr = tid >> 2;          // 0..63
    int lc = (tid & 3) * 4;     // 0,4,8,12
    const float* Ap = A + (size_t)(bm + lr) * K + lc;
    const float* Wp = W + (size_t)(bn + lr) * K + lc;
    float acc[4][4] = {};
    for (int k0 = 0; k0 < K; k0 += 16) {
        float4 av = *(const float4*)(Ap + k0);
        float4 wv = *(const float4*)(Wp + k0);
        As[lc+0][lr]=av.x; As[lc+1][lr]=av.y; As[lc+2][lr]=av.z; As[lc+3][lr]=av.w;
        Ws[lc+0][lr]=wv.x; Ws[lc+1][lr]=wv.y; Ws[lc+2][lr]=wv.z; Ws[lc+3][lr]=wv.w;
        __syncthreads();
#pragma unroll
        for (int kk = 0; kk < 16; kk++) {
            float a0=As[kk][ty*4+0], a1=As[kk][ty*4+1], a2=As[kk][ty*4+2], a3=As[kk][ty*4+3];
            float w0=Ws[kk][tx*4+0], w1=Ws[kk][tx*4+1], w2=Ws[kk][tx*4+2], w3=Ws[kk][tx*4+3];
            acc[0][0]=fmaf(a0,w0,acc[0][0]); acc[0][1]=fmaf(a0,w1,acc[0][1]);
            acc[0][2]=fmaf(a0,w2,acc[0][2]); acc[0][3]=fmaf(a0,w3,acc[0][3]);
            acc[1][0]=fmaf(a1,w0,acc[1][0]); acc[1][1]=fmaf(a1,w1,acc[1][1]);
            acc[1][2]=fmaf(a1,w2,acc[1][2]); acc[1][3]=fmaf(a1,w3,acc[1][3]);
            acc[2][0]=fmaf(a2,w0,acc[2][0]); acc[2][1]=fmaf(a2,w1,acc[2][1]);
            acc[2][2]=fmaf(a2,w2,acc[2][2]); acc[2][3]=fmaf(a2,w3,acc[2][3]);
            acc[3][0]=fmaf(a3,w0,acc[3][0]); acc[3][1]=fmaf(a3,w1,acc[3][1]);
            acc[3][2]=fmaf(a3,w2,acc[3][2]); acc[3][3]=fmaf(a3,w3,acc[3][3]);
        }
        __syncthreads();
    }
#pragma unroll
    for (int i = 0; i < 4; i++) {
        int m = bm + ty*4 + i;
#pragma unroll
        for (int j = 0; j < 4; j++) {
            int n = bn + tx*4 + j;
            float val = acc[i][j] + bias[n];
            if (MODE == 0) {
                out[(size_t)m * N + n] = val;
            } else {
                val += resid[(size_t)m * N + n];
                // y[bd][c][t]: bd = m/32, t = m%32, c = n  (N=512, T=32)
                out[(size_t)(m >> 5) * (512*32) + (size_t)n * 32 + (m & 31)] = val;
            }
        }
    }
}

// ---------------- RPE: h = silu(tproj + feats@dw.T + db) ----------------
__global__ __launch_bounds__(256) void rpe_h_kernel(
    const float* __restrict__ tproj, const int* __restrict__ fi,
    const float* __restrict__ qdw, const float* __restrict__ qdb,
    const float* __restrict__ kdw, const float* __restrict__ kdb,
    const float* __restrict__ vdw, const float* __restrict__ vdb,
    float* __restrict__ h)
{
    int idx = blockIdx.x * 256 + threadIdx.x;      // [p,b,t,s,c]
    int c = idx & 511;
    int s = (idx >> 9) & 31;
    int t = (idx >> 14) & 31;
    int b = (idx >> 19) & 1;
    int p = idx >> 20;
    int d = fi[b*TT + t] - fi[b*TT + s];
    float df = (float)d;
    float f0 = log1pf(fmaxf(df, 0.f));
    float f1 = log1pf(fmaxf(-df, 0.f));
    float f2 = (d == 0) ? 1.f : 0.f;
    const float* dw = (p == 0) ? qdw : ((p == 1) ? kdw : vdw);
    const float* db = (p == 0) ? qdb : ((p == 1) ? kdb : vdb);
    float e = tproj[(size_t)((p*BB + b)*TT + t) * CC + c]
            + dw[c*3+0]*f0 + dw[c*3+1]*f1 + dw[c*3+2]*f2 + db[c];
    float sig = 1.f / (1.f + __expf(-e));
    h[idx] = e * sig;
}

// ---------------- attention: block per (b,d,h) ----------------
__global__ __launch_bounds__(256) void attn_kernel(
    const float* __restrict__ qkv, const float* __restrict__ R,
    const int* __restrict__ mask, float* __restrict__ ao)
{
    __shared__ float qs[32*65], ks[32*65], vs[32*65];
    __shared__ float at[32*33];
    __shared__ int   msk[32];
    int tid = threadIdx.x;
    int h  = blockIdx.x & 7;
    int bd = blockIdx.x >> 3;
    int b  = bd >> 9;
    const float* base = qkv + (size_t)bd * TT * N_QKV + h * FF;
    for (int e = tid; e < 32*16; e += 256) {
        int t = e >> 4, f = (e & 15) * 4;
        const float* rowp = base + (size_t)t * N_QKV + f;
        float4 q4 = *(const float4*)(rowp);
        float4 k4 = *(const float4*)(rowp + 512);
        float4 v4 = *(const float4*)(rowp + 1024);
        float* qd = &qs[t*65+f]; qd[0]=q4.x*SCALE; qd[1]=q4.y*SCALE; qd[2]=q4.z*SCALE; qd[3]=q4.w*SCALE;
        float* kd = &ks[t*65+f]; kd[0]=k4.x; kd[1]=k4.y; kd[2]=k4.z; kd[3]=k4.w;
        float* vd = &vs[t*65+f]; vd[0]=v4.x; vd[1]=v4.y; vd[2]=v4.z; vd[3]=v4.w;
    }
    if (tid < 32) msk[tid] = mask[b*TT + tid];
    __syncthreads();

    const float* Rq = R + (size_t)(0*BB + b) * (TT*TT*CC) + h*FF;
    const float* Rk = R + (size_t)(1*BB + b) * (TT*TT*CC) + h*FF;
    const float* Rv = R + (size_t)(2*BB + b) * (TT*TT*CC) + h*FF;

#pragma unroll
    for (int pi = 0; pi < 4; pi++) {
        int pid = pi*256 + tid;
        int t = pid >> 5, s = pid & 31;
        const float* rk = Rk + (size_t)(t*TT + s) * CC;
        const float* rq = Rq + (size_t)(s*TT + t) * CC;
        float acc = 0.f, accq = 0.f;
#pragma unroll
        for (int f = 0; f < FF; f += 4) {
            float4 rk4 = *(const float4*)(rk + f);
            float4 rq4 = *(const float4*)(rq + f);
            float q0=qs[t*65+f], q1=qs[t*65+f+1], q2=qs[t*65+f+2], q3=qs[t*65+f+3];
            float k0=ks[s*65+f], k1=ks[s*65+f+1], k2=ks[s*65+f+2], k3=ks[s*65+f+3];
            acc  = fmaf(q0, k0 + rk4.x, acc);
            acc  = fmaf(q1, k1 + rk4.y, acc);
            acc  = fmaf(q2, k2 + rk4.z, acc);
            acc  = fmaf(q3, k3 + rk4.w, acc);
            accq = fmaf(k0, rq4.x, accq);
            accq = fmaf(k1, rq4.y, accq);
            accq = fmaf(k2, rq4.z, accq);
            accq = fmaf(k3, rq4.w, accq);
        }
        float val = acc + SCALE * accq;
        if (msk[t] != msk[s]) val = -1e30f;
        at[t*33 + s] = val;
    }
    __syncthreads();

    if (tid < 32) {
        int t = tid;
        float mx = -1e30f;
#pragma unroll
        for (int s = 0; s < 32; s++) mx = fmaxf(mx, at[t*33+s]);
        float ex[32]; float sum = 0.f;
#pragma unroll
        for (int s = 0; s < 32; s++) { ex[s] = __expf(at[t*33+s] - mx); sum += ex[s]; }
        float inv = 1.f / sum;
#pragma unroll
        for (int s = 0; s < 32; s++) at[t*33+s] = ex[s] * inv;
    }
    __syncthreads();

    float* aout = ao + (size_t)bd * TT * CC + h * FF;
#pragma unroll
    for (int oi = 0; oi < 8; oi++) {
        int o = oi*256 + tid;
        int t = o >> 6, f = o & 63;
        const float* rv = Rv + (size_t)t * TT * CC + f;
        float acc = 0.f;
#pragma unroll
        for (int s = 0; s < 32; s++)
            acc = fmaf(at[t*33+s], vs[s*65+f] + rv[(size_t)s*CC], acc);
        aout[(size_t)t*CC + f] = acc;
    }
}

// ---------------- launch ----------------
extern "C" void kernel_launch(void* const* d_in, const int* in_sizes, int n_in,
                              void* d_out, int out_size)
{
    const float* x      = (const float*)d_in[0];
    const float* temb   = (const float*)d_in[1];
    const int*   fi     = (const int*)  d_in[2];
    const int*   amask  = (const int*)  d_in[3];
    const float* norm_w = (const float*)d_in[4];
    const float* norm_b = (const float*)d_in[5];
    const float* qkv_w  = (const float*)d_in[6];
    const float* qkv_b  = (const float*)d_in[7];
    const float* proj_w = (const float*)d_in[8];
    const float* proj_b = (const float*)d_in[9];
    // per-p params at 10 + p*6: dist_w, dist_b, time_w, time_b, out_w, out_b
    const float* dist_w[3]; const float* dist_b[3];
    const float* time_w[3]; const float* time_b[3];
    const float* out_w[3];  const float* out_b[3];
    for (int p = 0; p < 3; p++) {
        dist_w[p] = (const float*)d_in[10 + p*6 + 0];
        dist_b[p] = (const float*)d_in[10 + p*6 + 1];
        time_w[p] = (const float*)d_in[10 + p*6 + 2];
        time_b[p] = (const float*)d_in[10 + p*6 + 3];
        out_w[p]  = (const float*)d_in[10 + p*6 + 4];
        out_b[p]  = (const float*)d_in[10 + p*6 + 5];
    }

    float *xt, *qkvb, *tprj, *hbuf, *Rbuf, *ao;
    cudaGetSymbolAddress((void**)&xt,   g_xt);
    cudaGetSymbolAddress((void**)&qkvb, g_qkv);
    cudaGetSymbolAddress((void**)&tprj, g_tprj);
    cudaGetSymbolAddress((void**)&hbuf, g_h);
    cudaGetSymbolAddress((void**)&Rbuf, g_R);
    cudaGetSymbolAddress((void**)&ao,   g_ao);

    // 1. GroupNorm + transpose -> xt [B,D,T,C]
    groupnorm_kernel<<<BB*DD, 512>>>(x, norm_w, norm_b, xt);

    // 2. QKV GEMM: [32768,512] @ [1536,512]^T
    gemm_nt<0><<<dim3(N_QKV/64, M_QKV/64), 256>>>(xt, qkv_w, qkv_b, qkvb, nullptr,
                                                  M_QKV, N_QKV, CC);

    // 3. temb projections: [64,1024] @ [512,1024]^T per p
    for (int p = 0; p < 3; p++)
        gemm_nt<0><<<dim3(CC/64, 1), 256>>>(temb, time_w[p], time_b[p],
                                            tprj + (size_t)p*BB*TT*CC, nullptr,
                                            BB*TT, CC, TDIM);

    // 4. h = silu(emb)
    rpe_h_kernel<<<(3*BB*TT*TT*CC)/256, 256>>>(tprj, fi,
        dist_w[0], dist_b[0], dist_w[1], dist_b[1], dist_w[2], dist_b[2], hbuf);

    // 5. R = h @ out_w^T + out_b per p: [2048,512] @ [512,512]^T
    for (int p = 0; p < 3; p++)
        gemm_nt<0><<<dim3(CC/64, (BB*TT*TT)/64), 256>>>(
            hbuf + (size_t)p*BB*TT*TT*CC, out_w[p], out_b[p],
            Rbuf + (size_t)p*BB*TT*TT*CC, nullptr, BB*TT*TT, CC, CC);

    // 6. attention
    attn_kernel<<<BB*DD*HH, 256>>>(qkvb, Rbuf, amask, ao);

    // 7. proj + residual + transpose -> d_out [B,D,C,T]
    gemm_nt<1><<<dim3(CC/64, M_QKV/64), 256>>>(ao, proj_w, proj_b,
                                               (float*)d_out, xt, M_QKV, CC, CC);
}

// round 5
// speedup vs baseline: 1.8566x; 1.8566x over previous
#include <cuda_runtime.h>
#include <cstdint>

// Problem constants
#define BB 2
#define DD 512
#define CC 512
#define TT 32
#define TDIM 1024
#define HH 8
#define FF 64
#define SCALE 0.125f   // F^-0.5

#define M_QKV (BB*DD*TT)       // 32768
#define N_QKV (3*CC)           // 1536

// ---------------- scratch ----------------
__device__ float g_xt  [BB*DD*TT*CC];        // normalized, transposed x  [B,D,T,C]
__device__ float g_qkv [BB*DD*TT*3*CC];      // [B,D,T,3C]
__device__ float g_tprj[3*BB*TT*CC];         // [p,B,T,C]
__device__ float g_h   [3*BB*TT*TT*CC];      // silu(emb) [p,B,T,S,C]
__device__ float g_R   [3*BB*TT*TT*CC];      // rpe bias  [p,B,T,S,C]
__device__ float g_ao  [BB*DD*TT*CC];        // attention output pre-proj [B,D,T,C]

// ---------------- GroupNorm + transpose ----------------
__global__ __launch_bounds__(512) void groupnorm_kernel(
    const float* __restrict__ x, const float* __restrict__ w,
    const float* __restrict__ bv, float* __restrict__ xt)
{
    int bd = blockIdx.x;
    int c  = threadIdx.x;
    const float* xr = x + (size_t)bd * CC * TT + (size_t)c * TT;
    float v[TT];
    float s = 0.f, ss = 0.f;
#pragma unroll
    for (int i = 0; i < TT/4; i++) {
        float4 t4 = *(const float4*)(xr + i*4);
        v[i*4+0]=t4.x; v[i*4+1]=t4.y; v[i*4+2]=t4.z; v[i*4+3]=t4.w;
        s += t4.x+t4.y+t4.z+t4.w;
        ss += t4.x*t4.x + t4.y*t4.y + t4.z*t4.z + t4.w*t4.w;
    }
#pragma unroll
    for (int off = 8; off >= 1; off >>= 1) {
        s  += __shfl_xor_sync(0xffffffffu, s,  off);
        ss += __shfl_xor_sync(0xffffffffu, ss, off);
    }
    float mean = s * (1.f/512.f);
    float var  = ss * (1.f/512.f) - mean*mean;
    float rstd = rsqrtf(var + 1e-5f);
    float gw = w[c] * rstd;
    float gb = bv[c] - mean * gw;
    float* dst = xt + (size_t)bd * TT * CC + c;
#pragma unroll
    for (int t = 0; t < TT; t++) dst[(size_t)t*CC] = fmaf(v[t], gw, gb);
}

// ---------------- tf32 tensor-core NT GEMM ----------------
// out[m,n] = sum_k A[m,k] * W[n,k] + bias[n]
// BM=128, BN=128, BK=32, 256 threads, 8 warps (4 in M x 2 in N), warp tile 32x64.
// mma.sync.m16n8k8 tf32, fp32 accumulate. Operands rounded with cvt.rna.
// Weight/bias selected per M-stripe (rows_per_w) or per blockIdx.z (gridDim.z>1).
// mode 0: plain row-major store (guarded by m<M).
// mode 1: val += resid[m*N+n], store transposed as out[(m/32)][n][m%32] (N=512,T=32).
__device__ __forceinline__ unsigned f2tf(float x) {
    unsigned u;
    asm("cvt.rna.tf32.f32 %0, %1;" : "=r"(u) : "f"(x));
    return u;
}

__global__ __launch_bounds__(256, 2) void gemm_tf32(
    const float* __restrict__ A,
    const float* __restrict__ W0, const float* __restrict__ W1, const float* __restrict__ W2,
    const float* __restrict__ B0, const float* __restrict__ B1, const float* __restrict__ B2,
    float* __restrict__ out, const float* __restrict__ resid,
    int M, int N, int K, int rows_per_w, size_t out_z_stride, int mode)
{
    __shared__ float As[128][36];
    __shared__ float Bs[128][36];

    int bm = blockIdx.y * 128, bn = blockIdx.x * 128;
    int p = (gridDim.z > 1) ? blockIdx.z : (bm / rows_per_w);
    const float* W    = (p == 0) ? W0 : ((p == 1) ? W1 : W2);
    const float* bias = (p == 0) ? B0 : ((p == 1) ? B1 : B2);
    float* outp = out + (size_t)blockIdx.z * out_z_stride;

    int tid  = threadIdx.x;
    int warp = tid >> 5, lane = tid & 31;
    int g = lane >> 2, tg = lane & 3;
    int wm = (warp >> 1) * 32;      // warp M offset (0,32,64,96)
    int wn = (warp & 1) * 64;       // warp N offset (0,64)

    int lrow = tid >> 1;            // 0..127
    int lk   = (tid & 1) * 16;      // 0 or 16

    float acc[2][8][4];
#pragma unroll
    for (int i = 0; i < 2; i++)
#pragma unroll
        for (int j = 0; j < 8; j++)
#pragma unroll
            for (int r = 0; r < 4; r++) acc[i][j][r] = 0.f;

    bool a_ok = (bm + lrow) < M;     // M may be < 128 (tproj); N,K always tile-divisible
    const float* Ap = A + (size_t)(bm + lrow) * K + lk;
    const float* Wp = W + (size_t)(bn + lrow) * K + lk;

    for (int k0 = 0; k0 < K; k0 += 32) {
#pragma unroll
        for (int v = 0; v < 4; v++) {
            float4 av = a_ok ? *(const float4*)(Ap + k0 + v*4)
                             : make_float4(0.f, 0.f, 0.f, 0.f);
            float4 wv = *(const float4*)(Wp + k0 + v*4);
            int kc = lk + v*4;
            As[lrow][kc+0] = __uint_as_float(f2tf(av.x));
            As[lrow][kc+1] = __uint_as_float(f2tf(av.y));
            As[lrow][kc+2] = __uint_as_float(f2tf(av.z));
            As[lrow][kc+3] = __uint_as_float(f2tf(av.w));
            Bs[lrow][kc+0] = __uint_as_float(f2tf(wv.x));
            Bs[lrow][kc+1] = __uint_as_float(f2tf(wv.y));
            Bs[lrow][kc+2] = __uint_as_float(f2tf(wv.z));
            Bs[lrow][kc+3] = __uint_as_float(f2tf(wv.w));
        }
        __syncthreads();
#pragma unroll
        for (int ks = 0; ks < 4; ks++) {
            int kk = ks * 8;
            unsigned a[2][4];
#pragma unroll
            for (int i = 0; i < 2; i++) {
                int m = wm + i*16 + g;
                a[i][0] = __float_as_uint(As[m    ][kk + tg    ]);
                a[i][1] = __float_as_uint(As[m + 8][kk + tg    ]);
                a[i][2] = __float_as_uint(As[m    ][kk + tg + 4]);
                a[i][3] = __float_as_uint(As[m + 8][kk + tg + 4]);
            }
            unsigned b[8][2];
#pragma unroll
            for (int j = 0; j < 8; j++) {
                int n = wn + j*8 + g;
                b[j][0] = __float_as_uint(Bs[n][kk + tg    ]);
                b[j][1] = __float_as_uint(Bs[n][kk + tg + 4]);
            }
#pragma unroll
            for (int i = 0; i < 2; i++)
#pragma unroll
                for (int j = 0; j < 8; j++) {
                    asm volatile(
                        "mma.sync.aligned.m16n8k8.row.col.f32.tf32.tf32.f32 "
                        "{%0,%1,%2,%3}, {%4,%5,%6,%7}, {%8,%9}, {%0,%1,%2,%3};\n"
                        : "+f"(acc[i][j][0]), "+f"(acc[i][j][1]),
                          "+f"(acc[i][j][2]), "+f"(acc[i][j][3])
                        : "r"(a[i][0]), "r"(a[i][1]), "r"(a[i][2]), "r"(a[i][3]),
                          "r"(b[j][0]), "r"(b[j][1]));
                }
        }
        __syncthreads();
    }

    // epilogue
#pragma unroll
    for (int i = 0; i < 2; i++) {
        int m0 = bm + wm + i*16 + g;
        int m1 = m0 + 8;
#pragma unroll
        for (int j = 0; j < 8; j++) {
            int n0 = bn + wn + j*8 + tg*2;
            float bn0 = bias[n0], bn1 = bias[n0+1];
            float v00 = acc[i][j][0] + bn0, v01 = acc[i][j][1] + bn1;
            float v10 = acc[i][j][2] + bn0, v11 = acc[i][j][3] + bn1;
            if (mode == 0) {
                if (m0 < M) { outp[(size_t)m0*N + n0] = v00; outp[(size_t)m0*N + n0+1] = v01; }
                if (m1 < M) { outp[(size_t)m1*N + n0] = v10; outp[(size_t)m1*N + n0+1] = v11; }
            } else {
                v00 += resid[(size_t)m0*N + n0];
                v01 += resid[(size_t)m0*N + n0+1];
                v10 += resid[(size_t)m1*N + n0];
                v11 += resid[(size_t)m1*N + n0+1];
                // y[bd][c][t]: bd=m/32, c=n, t=m%32 (N=512, T=32)
                size_t b0 = (size_t)(m0 >> 5) * (512*32);
                size_t b1 = (size_t)(m1 >> 5) * (512*32);
                outp[b0 + (size_t)(n0  )*32 + (m0 & 31)] = v00;
                outp[b0 + (size_t)(n0+1)*32 + (m0 & 31)] = v01;
                outp[b1 + (size_t)(n0  )*32 + (m1 & 31)] = v10;
                outp[b1 + (size_t)(n0+1)*32 + (m1 & 31)] = v11;
            }
        }
    }
}

// ---------------- RPE: h = silu(tproj + feats@dw.T + db) ----------------
__global__ __launch_bounds__(256) void rpe_h_kernel(
    const float* __restrict__ tproj, const int* __restrict__ fi,
    const float* __restrict__ qdw, const float* __restrict__ qdb,
    const float* __restrict__ kdw, const float* __restrict__ kdb,
    const float* __restrict__ vdw, const float* __restrict__ vdb,
    float* __restrict__ h)
{
    int idx = blockIdx.x * 256 + threadIdx.x;      // [p,b,t,s,c]
    int c = idx & 511;
    int s = (idx >> 9) & 31;
    int t = (idx >> 14) & 31;
    int b = (idx >> 19) & 1;
    int p = idx >> 20;
    int d = fi[b*TT + t] - fi[b*TT + s];
    float df = (float)d;
    float f0 = log1pf(fmaxf(df, 0.f));
    float f1 = log1pf(fmaxf(-df, 0.f));
    float f2 = (d == 0) ? 1.f : 0.f;
    const float* dw = (p == 0) ? qdw : ((p == 1) ? kdw : vdw);
    const float* db = (p == 0) ? qdb : ((p == 1) ? kdb : vdb);
    float e = tproj[(size_t)((p*BB + b)*TT + t) * CC + c]
            + dw[c*3+0]*f0 + dw[c*3+1]*f1 + dw[c*3+2]*f2 + db[c];
    float sig = 1.f / (1.f + __expf(-e));
    h[idx] = e * sig;
}

// ---------------- attention: block per (b,d,h) ----------------
__global__ __launch_bounds__(256) void attn_kernel(
    const float* __restrict__ qkv, const float* __restrict__ R,
    const int* __restrict__ mask, float* __restrict__ ao)
{
    __shared__ float qs[32*65], ks[32*65], vs[32*65];
    __shared__ float at[32*33];
    __shared__ int   msk[32];
    int tid = threadIdx.x;
    int h  = blockIdx.x & 7;
    int bd = blockIdx.x >> 3;
    int b  = bd >> 9;
    const float* base = qkv + (size_t)bd * TT * N_QKV + h * FF;
    for (int e = tid; e < 32*16; e += 256) {
        int t = e >> 4, f = (e & 15) * 4;
        const float* rowp = base + (size_t)t * N_QKV + f;
        float4 q4 = *(const float4*)(rowp);
        float4 k4 = *(const float4*)(rowp + 512);
        float4 v4 = *(const float4*)(rowp + 1024);
        float* qd = &qs[t*65+f]; qd[0]=q4.x*SCALE; qd[1]=q4.y*SCALE; qd[2]=q4.z*SCALE; qd[3]=q4.w*SCALE;
        float* kd = &ks[t*65+f]; kd[0]=k4.x; kd[1]=k4.y; kd[2]=k4.z; kd[3]=k4.w;
        float* vd = &vs[t*65+f]; vd[0]=v4.x; vd[1]=v4.y; vd[2]=v4.z; vd[3]=v4.w;
    }
    if (tid < 32) msk[tid] = mask[b*TT + tid];
    __syncthreads();

    const float* Rq = R + (size_t)(0*BB + b) * (TT*TT*CC) + h*FF;
    const float* Rk = R + (size_t)(1*BB + b) * (TT*TT*CC) + h*FF;
    const float* Rv = R + (size_t)(2*BB + b) * (TT*TT*CC) + h*FF;

#pragma unroll
    for (int pi = 0; pi < 4; pi++) {
        int pid = pi*256 + tid;
        int t = pid >> 5, s = pid & 31;
        const float* rk = Rk + (size_t)(t*TT + s) * CC;
        const float* rq = Rq + (size_t)(s*TT + t) * CC;
        float acc = 0.f, accq = 0.f;
#pragma unroll
        for (int f = 0; f < FF; f += 4) {
            float4 rk4 = *(const float4*)(rk + f);
            float4 rq4 = *(const float4*)(rq + f);
            float q0=qs[t*65+f], q1=qs[t*65+f+1], q2=qs[t*65+f+2], q3=qs[t*65+f+3];
            float k0=ks[s*65+f], k1=ks[s*65+f+1], k2=ks[s*65+f+2], k3=ks[s*65+f+3];
            acc  = fmaf(q0, k0 + rk4.x, acc);
            acc  = fmaf(q1, k1 + rk4.y, acc);
            acc  = fmaf(q2, k2 + rk4.z, acc);
            acc  = fmaf(q3, k3 + rk4.w, acc);
            accq = fmaf(k0, rq4.x, accq);
            accq = fmaf(k1, rq4.y, accq);
            accq = fmaf(k2, rq4.z, accq);
            accq = fmaf(k3, rq4.w, accq);
        }
        float val = acc + SCALE * accq;
        if (msk[t] != msk[s]) val = -1e30f;
        at[t*33 + s] = val;
    }
    __syncthreads();

    if (tid < 32) {
        int t = tid;
        float mx = -1e30f;
#pragma unroll
        for (int s = 0; s < 32; s++) mx = fmaxf(mx, at[t*33+s]);
        float ex[32]; float sum = 0.f;
#pragma unroll
        for (int s = 0; s < 32; s++) { ex[s] = __expf(at[t*33+s] - mx); sum += ex[s]; }
        float inv = 1.f / sum;
#pragma unroll
        for (int s = 0; s < 32; s++) at[t*33+s] = ex[s] * inv;
    }
    __syncthreads();

    float* aout = ao + (size_t)bd * TT * CC + h * FF;
#pragma unroll
    for (int oi = 0; oi < 8; oi++) {
        int o = oi*256 + tid;
        int t = o >> 6, f = o & 63;
        const float* rv = Rv + (size_t)t * TT * CC + f;
        float acc = 0.f;
#pragma unroll
        for (int s = 0; s < 32; s++)
            acc = fmaf(at[t*33+s], vs[s*65+f] + rv[(size_t)s*CC], acc);
        aout[(size_t)t*CC + f] = acc;
    }
}

// ---------------- launch ----------------
extern "C" void kernel_launch(void* const* d_in, const int* in_sizes, int n_in,
                              void* d_out, int out_size)
{
    const float* x      = (const float*)d_in[0];
    const float* temb   = (const float*)d_in[1];
    const int*   fi     = (const int*)  d_in[2];
    const int*   amask  = (const int*)  d_in[3];
    const float* norm_w = (const float*)d_in[4];
    const float* norm_b = (const float*)d_in[5];
    const float* qkv_w  = (const float*)d_in[6];
    const float* qkv_b  = (const float*)d_in[7];
    const float* proj_w = (const float*)d_in[8];
    const float* proj_b = (const float*)d_in[9];
    const float* dist_w[3]; const float* dist_b[3];
    const float* time_w[3]; const float* time_b[3];
    const float* out_w[3];  const float* out_b[3];
    for (int p = 0; p < 3; p++) {
        dist_w[p] = (const float*)d_in[10 + p*6 + 0];
        dist_b[p] = (const float*)d_in[10 + p*6 + 1];
        time_w[p] = (const float*)d_in[10 + p*6 + 2];
        time_b[p] = (const float*)d_in[10 + p*6 + 3];
        out_w[p]  = (const float*)d_in[10 + p*6 + 4];
        out_b[p]  = (const float*)d_in[10 + p*6 + 5];
    }

    float *xt, *qkvb, *tprj, *hbuf, *Rbuf, *ao;
    cudaGetSymbolAddress((void**)&xt,   g_xt);
    cudaGetSymbolAddress((void**)&qkvb, g_qkv);
    cudaGetSymbolAddress((void**)&tprj, g_tprj);
    cudaGetSymbolAddress((void**)&hbuf, g_h);
    cudaGetSymbolAddress((void**)&Rbuf, g_R);
    cudaGetSymbolAddress((void**)&ao,   g_ao);

    const int HUGE_ROWS = 1 << 30;

    // 1. GroupNorm + transpose -> xt [B,D,T,C]
    groupnorm_kernel<<<BB*DD, 512>>>(x, norm_w, norm_b, xt);

    // 2. QKV GEMM: [32768,512] @ [1536,512]^T  (tf32 tensor cores)
    gemm_tf32<<<dim3(N_QKV/128, M_QKV/128, 1), 256>>>(
        xt, qkv_w, qkv_w, qkv_w, qkv_b, qkv_b, qkv_b,
        qkvb, nullptr, M_QKV, N_QKV, CC, HUGE_ROWS, 0, 0);

    // 3. temb projections: one launch, z = p, [64,1024] @ [512,1024]^T
    gemm_tf32<<<dim3(CC/128, 1, 3), 256>>>(
        temb, time_w[0], time_w[1], time_w[2], time_b[0], time_b[1], time_b[2],
        tprj, nullptr, BB*TT, CC, TDIM, HUGE_ROWS, (size_t)BB*TT*CC, 0);

    // 4. h = silu(emb)
    rpe_h_kernel<<<(3*BB*TT*TT*CC)/256, 256>>>(tprj, fi,
        dist_w[0], dist_b[0], dist_w[1], dist_b[1], dist_w[2], dist_b[2], hbuf);

    // 5. R = h @ out_w[p]^T + out_b[p]: single launch over [6144,512]@[512,512]^T,
    //    weight stripe every 2048 rows
    gemm_tf32<<<dim3(CC/128, (3*BB*TT*TT)/128, 1), 256>>>(
        hbuf, out_w[0], out_w[1], out_w[2], out_b[0], out_b[1], out_b[2],
        Rbuf, nullptr, 3*BB*TT*TT, CC, CC, BB*TT*TT, 0, 0);

    // 6. attention
    attn_kernel<<<BB*DD*HH, 256>>>(qkvb, Rbuf, amask, ao);

    // 7. proj + residual + transpose -> d_out [B,D,C,T]
    gemm_tf32<<<dim3(CC/128, M_QKV/128, 1), 256>>>(
        ao, proj_w, proj_w, proj_w, proj_b, proj_b, proj_b,
        (float*)d_out, xt, M_QKV, CC, CC, HUGE_ROWS, 0, 1);
}